// round 6
// baseline (speedup 1.0000x reference)
#include <cuda_runtime.h>
#include <cuda_bf16.h>

// S4D: K[h, a+64b] = sum_n ( Qr[n][b]*Pr[n][a] - Qi[n][b]*Pi[n][a] )
//   P[n][a] = 2*Ck_n*w^a,  Q[n][b] = (w^64)^b,  w = exp(dt*A)
//
// Mode-pair f32x2 packing + XOR bank swizzle (col' = col ^ ((n2&7)<<1)).
// R4: cap regs at 128 (__launch_bounds__(128,4)) for 4 resident blocks /SM;
// phase 1 processes the two modes of a pair sequentially (scalar stores) to
// keep its register peak below phase 2's.

#define NP 16
#define LL 64

typedef unsigned long long u64;

__device__ __forceinline__ u64 ffma2(u64 a, u64 b, u64 c) {
    u64 d;
    asm("fma.rn.f32x2 %0, %1, %2, %3;" : "=l"(d) : "l"(a), "l"(b), "l"(c));
    return d;
}
__device__ __forceinline__ float f2sum(u64 v) {
    float2 f = *reinterpret_cast<float2*>(&v);
    return f.x + f.y;
}

__global__ __launch_bounds__(128, 4)
void s4d_kernel(const float* __restrict__ log_dt,
                const float* __restrict__ C,
                const float* __restrict__ log_A_real,
                const float* __restrict__ A_imag,
                float* __restrict__ out)
{
    __shared__ __align__(16) float2 PrP[NP][LL];
    __shared__ __align__(16) float2 PiP[NP][LL];
    __shared__ __align__(16) float2 QrP[NP][LL];
    __shared__ __align__(16) float2 QiP[NP][LL];   // holds -qi

    const int h   = blockIdx.x;
    const int tid = threadIdx.x;

    // ---------------- Phase 1: build tables (low register pressure) -------
    {
        const int n2 = tid & 15;
        const int s  = tid >> 4;          // slice 0..7 (8 entries each)
        const int xr = (n2 & 7) << 1;     // column swizzle
        const float dt = expf(log_dt[h]);

        float* PrF = (float*)PrP;
        float* PiF = (float*)PiP;
        float* QrF = (float*)QrP;
        float* QiF = (float*)QiP;

        // two modes of the pair handled sequentially: small live set
        #pragma unroll 1
        for (int c = 0; c < 2; c++) {
            const int m = 2 * n2 + c;
            const float Ar = -expf(log_A_real[h * 32 + m]);
            const float Ai = A_imag[h * 32 + m];
            const float dr = dt * Ar, di = dt * Ai;

            float er, sn, cs;

            // w = exp(dt*A)
            er = expf(dr); sincosf(di, &sn, &cs);
            const float wr = er * cs, wi = er * sn;

            // P0 = 2*C*(w-1)/A
            {
                const float inv = 1.0f / (Ar * Ar + Ai * Ai);
                const float nr = wr - 1.0f, ni = wi;
                const float gr = (nr * Ar + ni * Ai) * inv;
                const float gi = (ni * Ar - nr * Ai) * inv;
                const float Cr = C[(h * 32 + m) * 2 + 0];
                const float Ci = C[(h * 32 + m) * 2 + 1];
                const float p0r = 2.0f * (Cr * gr - Ci * gi);
                const float p0i = 2.0f * (Cr * gi + Ci * gr);

                // slice start: p = P0 * w^{8s}
                const float a0f = (float)(8 * s);
                er = expf(dr * a0f); sincosf(di * a0f, &sn, &cs);
                float pr = p0r * (er * cs) - p0i * (er * sn);
                float pi = p0r * (er * sn) + p0i * (er * cs);

                #pragma unroll
                for (int k = 0; k < 8; k++) {
                    const int idx = (n2 * LL + ((8 * s + k) ^ xr)) * 2 + c;
                    PrF[idx] = pr;
                    PiF[idx] = pi;
                    const float t = pr * wr - pi * wi;
                    pi = pr * wi + pi * wr;
                    pr = t;
                }
            }

            // Q: wJ = w^64 (direct), slice start (w^64)^{8s} = exp(512 s dtA)
            {
                er = expf(64.0f * dr); sincosf(64.0f * di, &sn, &cs);
                const float wJr = er * cs, wJi = er * sn;

                const float b0f = 512.0f * (float)s;
                er = expf(dr * b0f); sincosf(di * b0f, &sn, &cs);
                float qr = er * cs, qi = er * sn;

                #pragma unroll
                for (int k = 0; k < 8; k++) {
                    const int idx = (n2 * LL + ((8 * s + k) ^ xr)) * 2 + c;
                    QrF[idx] =  qr;
                    QiF[idx] = -qi;
                    const float t = qr * wJr - qi * wJi;
                    qi = qr * wJi + qi * wJr;
                    qr = t;
                }
            }
        }
    }
    __syncthreads();

    // ---------------- Phase 2: 64x64 contraction, 8b x 4a tiles ----------
    const int tx = tid & 15;
    const int ty = tid >> 4;          // 0..7
    const int b0 = 8 * ty;
    const int aA = 2 * tx;            // owns a in {aA, aA+1, aA+32, aA+33}

    u64 acc[8][4];
    #pragma unroll
    for (int i = 0; i < 8; i++)
        #pragma unroll
        for (int j = 0; j < 4; j++)
            acc[i][j] = 0ull;

    #pragma unroll
    for (int n2 = 0; n2 < NP; n2++) {
        const int x  = (n2 & 7) << 1;
        const int cA = aA ^ x;        // even; cA+32 covers the high a-pair

        // -------- real half: acc += qr * pr --------
        {
            const ulonglong2 pA = *(const ulonglong2*)&PrP[n2][cA];
            const ulonglong2 pB = *(const ulonglong2*)&PrP[n2][cA + 32];
            const u64 p[4] = {pA.x, pA.y, pB.x, pB.y};
            u64 q[8];
            #pragma unroll
            for (int k = 0; k < 4; k++) {
                const ulonglong2 t = *(const ulonglong2*)&QrP[n2][(b0 + 2 * k) ^ x];
                q[2 * k] = t.x; q[2 * k + 1] = t.y;
            }
            #pragma unroll
            for (int i = 0; i < 8; i++)
                #pragma unroll
                for (int j = 0; j < 4; j++)
                    acc[i][j] = ffma2(q[i], p[j], acc[i][j]);
        }
        // -------- imag half: acc += (-qi) * pi --------
        {
            const ulonglong2 pA = *(const ulonglong2*)&PiP[n2][cA];
            const ulonglong2 pB = *(const ulonglong2*)&PiP[n2][cA + 32];
            const u64 p[4] = {pA.x, pA.y, pB.x, pB.y};
            u64 q[8];
            #pragma unroll
            for (int k = 0; k < 4; k++) {
                const ulonglong2 t = *(const ulonglong2*)&QiP[n2][(b0 + 2 * k) ^ x];
                q[2 * k] = t.x; q[2 * k + 1] = t.y;
            }
            #pragma unroll
            for (int i = 0; i < 8; i++)
                #pragma unroll
                for (int j = 0; j < 4; j++)
                    acc[i][j] = ffma2(q[i], p[j], acc[i][j]);
        }
    }

    // ---------------- Store: reduce mode pairs, STG.64 coalesced ----------
    float* o = out + (size_t)h * (LL * LL);
    #pragma unroll
    for (int i = 0; i < 8; i++) {
        float* row = o + (b0 + i) * LL;
        *reinterpret_cast<float2*>(row + aA) =
            make_float2(f2sum(acc[i][0]), f2sum(acc[i][1]));
        *reinterpret_cast<float2*>(row + aA + 32) =
            make_float2(f2sum(acc[i][2]), f2sum(acc[i][3]));
    }
}

extern "C" void kernel_launch(void* const* d_in, const int* in_sizes, int n_in,
                              void* d_out, int out_size)
{
    const float* log_dt     = (const float*)d_in[0];
    const float* C          = (const float*)d_in[1];
    const float* log_A_real = (const float*)d_in[2];
    const float* A_imag     = (const float*)d_in[3];
    float*       out        = (float*)d_out;

    const int H = in_sizes[0];   // 1024
    s4d_kernel<<<H, 128>>>(log_dt, C, log_A_real, A_imag, out);
}